// round 2
// baseline (speedup 1.0000x reference)
#include <cuda_runtime.h>
#include <stdint.h>

// ============================================================================
// ShotNoise: out = Poisson(img * 12) / 12, bit-exact vs jax.random.poisson
// (key(42), threefry2x32, partitionable). Knuth branch proven exact in R1.
// Rejection branch: JAX's lax.while_loop overwrites k_out on EVERY accepting
// iteration until ALL pixels accepted -> result = k of LAST accept <= T_total.
// T_total computed in a first pass with lam_rejection = (lam<10 ? 1e5 : lam).
// ============================================================================

extern "C" {
__device__ float __nv_logf(float);
__device__ float __nv_log1pf(float);
}

#define TMAX 64

__device__ uint2 g_skK[TMAX + 1];   // knuth subkeys per iteration
__device__ uint2 g_skR0[TMAX + 1];  // rejection subkey_0 per iteration
__device__ uint2 g_skR1[TMAX + 1];  // rejection subkey_1 per iteration
__device__ int   g_T;               // global T_total for rejection loop

// ---------------------------------------------------------------------------
// threefry2x32 (JAX rotation schedule, 20 rounds)
// ---------------------------------------------------------------------------
__device__ __forceinline__ void tf2x32(uint32_t k0, uint32_t k1,
                                       uint32_t x0, uint32_t x1,
                                       uint32_t& o0, uint32_t& o1) {
    uint32_t ks2 = k0 ^ k1 ^ 0x1BD11BDAu;
    x0 += k0; x1 += k1;
#define TFR(r) { x0 += x1; x1 = __funnelshift_l(x1, x1, (r)); x1 ^= x0; }
    TFR(13) TFR(15) TFR(26) TFR(6)
    x0 += k1;  x1 += ks2 + 1u;
    TFR(17) TFR(29) TFR(16) TFR(24)
    x0 += ks2; x1 += k0 + 2u;
    TFR(13) TFR(15) TFR(26) TFR(6)
    x0 += k0;  x1 += k1 + 3u;
    TFR(17) TFR(29) TFR(16) TFR(24)
    x0 += k1;  x1 += ks2 + 4u;
    TFR(13) TFR(15) TFR(26) TFR(6)
    x0 += ks2; x1 += k0 + 5u;
#undef TFR
    o0 = x0; o1 = x1;
}

// ---------------------------------------------------------------------------
// Init: subkey chains from key(42)=(0,42), foldlike split; reset g_T.
// ---------------------------------------------------------------------------
__global__ void poisson_init_keys() {
    if (threadIdx.x != 0 || blockIdx.x != 0) return;
    g_T = 0;

    uint32_t r0 = 0u, r1 = 42u;                 // knuth: split(rng, 2)
    for (int t = 1; t <= TMAX; ++t) {
        uint32_t n0, n1, s0, s1;
        tf2x32(r0, r1, 0u, 0u, n0, n1);
        tf2x32(r0, r1, 0u, 1u, s0, s1);
        g_skK[t] = make_uint2(s0, s1);
        r0 = n0; r1 = n1;
    }
    uint32_t c0 = 0u, c1 = 42u;                 // rejection: split(key, 3)
    for (int t = 1; t <= TMAX; ++t) {
        uint32_t n0, n1, a0, a1, b0, b1;
        tf2x32(c0, c1, 0u, 0u, n0, n1);
        tf2x32(c0, c1, 0u, 1u, a0, a1);
        tf2x32(c0, c1, 0u, 2u, b0, b1);
        g_skR0[t] = make_uint2(a0, a1);
        g_skR1[t] = make_uint2(b0, b1);
        c0 = n0; c1 = n1;
    }
}

// ---------------------------------------------------------------------------
// partitionable uniform draw for flat element j
// ---------------------------------------------------------------------------
__device__ __forceinline__ float draw_uniform(uint2 key, uint32_t j) {
    uint32_t w0, w1;
    tf2x32(key.x, key.y, 0u, j, w0, w1);
    uint32_t bits = w0 ^ w1;
    return __uint_as_float((bits >> 9) | 0x3f800000u) - 1.0f;
}

// ---------------------------------------------------------------------------
// XLA's Lanczos lgamma (g=7, 8 coeffs), no-reflection path (input >= 1)
// ---------------------------------------------------------------------------
__device__ __forceinline__ float xla_lgamma(float input) {
    float z = __fadd_rn(input, -1.0f);
    float x = 0.99999999999980993f;
    x = __fadd_rn(x, __fdiv_rn( 676.5203681218851f,     __fadd_rn(z, 1.0f)));
    x = __fadd_rn(x, __fdiv_rn(-1259.1392167224028f,    __fadd_rn(z, 2.0f)));
    x = __fadd_rn(x, __fdiv_rn( 771.32342877765313f,    __fadd_rn(z, 3.0f)));
    x = __fadd_rn(x, __fdiv_rn(-176.61502916214059f,    __fadd_rn(z, 4.0f)));
    x = __fadd_rn(x, __fdiv_rn( 12.507343278686905f,    __fadd_rn(z, 5.0f)));
    x = __fadd_rn(x, __fdiv_rn(-0.13857109526572012f,   __fadd_rn(z, 6.0f)));
    x = __fadd_rn(x, __fdiv_rn( 9.9843695780195716e-6f, __fadd_rn(z, 7.0f)));
    x = __fadd_rn(x, __fdiv_rn( 1.5056327351493116e-7f, __fadd_rn(z, 8.0f)));
    float t = __fadd_rn(7.5f, z);
    float log_t = __fadd_rn(2.0149030205422647f, __nv_log1pf(__fdiv_rn(z, 7.5f)));
    float q = __fadd_rn(__fadd_rn(z, 0.5f), -__fdiv_rn(t, log_t));
    return __fadd_rn(__fadd_rn(0.9189385332046727f, __fmul_rn(q, log_t)),
                     __nv_logf(x));
}

// ---------------------------------------------------------------------------
// PTRS parameters + one accept test (exact XLA op ordering, no FMA)
// ---------------------------------------------------------------------------
struct Ptrs {
    float lam, log_lam, b, a, inv_alpha, v_r, two_a;
};

__device__ __forceinline__ Ptrs make_ptrs(float lam) {
    Ptrs p;
    p.lam       = lam;
    p.log_lam   = __nv_logf(lam);
    p.b         = __fadd_rn(0.931f, __fmul_rn(2.53f, __fsqrt_rn(lam)));
    p.a         = __fadd_rn(-0.059f, __fmul_rn(0.02483f, p.b));
    p.inv_alpha = __fadd_rn(1.1239f, __fdiv_rn(1.1328f, __fadd_rn(p.b, -3.4f)));
    p.v_r       = __fadd_rn(0.9277f, -__fdiv_rn(3.6224f, __fadd_rn(p.b, -2.0f)));
    p.two_a     = __fmul_rn(2.0f, p.a);
    return p;
}

__device__ __forceinline__ bool ptrs_try(const Ptrs& p, float u, float v,
                                         float& kf_out) {
    float us = __fadd_rn(0.5f, -fabsf(u));
    float kf = floorf(__fadd_rn(
        __fadd_rn(__fmul_rn(__fadd_rn(__fdiv_rn(p.two_a, us), p.b), u), p.lam),
        0.43f));
    kf_out = kf;
    bool accept1 = (us >= 0.07f) && (v <= p.v_r);
    if (accept1) return true;
    bool reject = (kf < 0.0f) || ((us < 0.013f) && (v > us));
    if (reject) return false;
    float s = __nv_logf(__fdiv_rn(__fmul_rn(v, p.inv_alpha),
                __fadd_rn(__fdiv_rn(p.a, __fmul_rn(us, us)), p.b)));
    float tt = __fadd_rn(__fadd_rn(-p.lam, __fmul_rn(kf, p.log_lam)),
                         -xla_lgamma(__fadd_rn(kf, 1.0f)));
    return (s <= tt);
}

// ---------------------------------------------------------------------------
// Pass 1: T_total = max over ALL pixels of first-accept iteration, with
// lam_rejection = (lam < 10 ? 1e5 : lam)  (JAX's masking).
// ---------------------------------------------------------------------------
__global__ void __launch_bounds__(256)
compute_T_kernel(const float* __restrict__ img, int n) {
    __shared__ uint2 skR0[TMAX + 1], skR1[TMAX + 1];
    __shared__ int warp_max[8];
    for (int i = threadIdx.x; i <= TMAX; i += blockDim.x) {
        skR0[i] = g_skR0[i];
        skR1[i] = g_skR1[i];
    }
    __syncthreads();

    int j = blockIdx.x * blockDim.x + threadIdx.x;
    int t_first = 0;
    if (j < n) {
        float lam = __fmul_rn(__ldg(img + j), 12.0f);
        float lam_eff = (lam < 10.0f) ? 1e5f : lam;
        Ptrs p = make_ptrs(lam_eff);
        uint32_t ju = (uint32_t)j;
#pragma unroll 1
        for (int t = 1; t <= TMAX; ++t) {
            float u = __fadd_rn(draw_uniform(skR0[t], ju), -0.5f);
            float v = draw_uniform(skR1[t], ju);
            float kf;
            if (ptrs_try(p, u, v, kf)) { t_first = t; break; }
        }
    }
    int wmax = __reduce_max_sync(0xFFFFFFFFu, t_first);
    int wid = threadIdx.x >> 5;
    if ((threadIdx.x & 31) == 0) warp_max[wid] = wmax;
    __syncthreads();
    if (threadIdx.x == 0) {
        int bmax = warp_max[0];
#pragma unroll
        for (int w = 1; w < 8; ++w) bmax = max(bmax, warp_max[w]);
        atomicMax(&g_T, bmax);
    }
}

// ---------------------------------------------------------------------------
// Pass 2: outputs. Knuth (exact, per-pixel early exit). Rejection: k of the
// LAST accepting iteration <= g_T — scan downward from g_T, first hit wins.
// ---------------------------------------------------------------------------
__global__ void __launch_bounds__(256)
shot_noise_kernel(const float* __restrict__ img, float* __restrict__ out, int n) {
    __shared__ uint2 skK[TMAX + 1], skR0[TMAX + 1], skR1[TMAX + 1];
    for (int i = threadIdx.x; i <= TMAX; i += blockDim.x) {
        skK[i]  = g_skK[i];
        skR0[i] = g_skR0[i];
        skR1[i] = g_skR1[i];
    }
    __syncthreads();

    int j = blockIdx.x * blockDim.x + threadIdx.x;
    if (j >= n) return;

    float lam = __fmul_rn(__ldg(img + j), 12.0f);
    uint32_t ju = (uint32_t)j;

    if (lam < 10.0f) {
        // ---- Knuth (bit-exact, proven) ----
        if (lam <= 0.0f) { out[j] = 0.0f; return; }
        float neg = -lam;
        float lp = 0.0f;
        int k = 0;
        int t = 1;
#pragma unroll 1
        while (lp > neg && t <= TMAX) {
            float u = draw_uniform(skK[t], ju);
            ++k;
            lp = __fadd_rn(lp, __nv_logf(u));
            ++t;
        }
        out[j] = __fdiv_rn((float)(k - 1), 12.0f);
    } else {
        // ---- Rejection: last accept <= T_total ----
        Ptrs p = make_ptrs(lam);
        int T = g_T;
        float kres = -1.0f;
#pragma unroll 1
        for (int t = T; t >= 1; --t) {
            float u = __fadd_rn(draw_uniform(skR0[t], ju), -0.5f);
            float v = draw_uniform(skR1[t], ju);
            float kf;
            if (ptrs_try(p, u, v, kf)) { kres = kf; break; }
        }
        out[j] = __fdiv_rn((float)(int)kres, 12.0f);
    }
}

// ---------------------------------------------------------------------------
extern "C" void kernel_launch(void* const* d_in, const int* in_sizes, int n_in,
                              void* d_out, int out_size) {
    const float* img = (const float*)d_in[0];
    float* out = (float*)d_out;
    int n = out_size;
    int blocks = (n + 255) / 256;

    poisson_init_keys<<<1, 32>>>();
    compute_T_kernel<<<blocks, 256>>>(img, n);
    shot_noise_kernel<<<blocks, 256>>>(img, out, n);
}

// round 3
// speedup vs baseline: 1.0826x; 1.0826x over previous
#include <cuda_runtime.h>
#include <stdint.h>

// ============================================================================
// ShotNoise: out = Poisson(img * 12) / 12, bit-exact vs jax.random.poisson
// (key(42), threefry2x32, partitionable). R2 proved the algorithm; R3 is the
// performance pass: per-thread task queues (divergence -> mean instead of
// warp-max), product-form Knuth (no logf per draw), block-compacted rejection
// phase, smem-staged coalesced output.
// ============================================================================

extern "C" {
__device__ float __nv_logf(float);
__device__ float __nv_log1pf(float);
__device__ float __nv_expf(float);
}

#define TMAX 64
#define CPT  8                    // pixels per thread
#define BLK  256
#define PPB  (BLK * CPT)          // pixels per block = 2048

__device__ uint2 g_skK[TMAX + 1];   // knuth subkeys
__device__ uint2 g_skR0[TMAX + 1];  // rejection subkey_0
__device__ uint2 g_skR1[TMAX + 1];  // rejection subkey_1
__device__ int   g_T;               // global rejection-loop iteration count
__device__ float g_effP[7];         // PTRS params for lam_eff = 1e5

// ---------------------------------------------------------------------------
// threefry2x32 (JAX rotation schedule, 20 rounds)
// ---------------------------------------------------------------------------
__device__ __forceinline__ void tf2x32(uint32_t k0, uint32_t k1,
                                       uint32_t x0, uint32_t x1,
                                       uint32_t& o0, uint32_t& o1) {
    uint32_t ks2 = k0 ^ k1 ^ 0x1BD11BDAu;
    x0 += k0; x1 += k1;
#define TFR(r) { x0 += x1; x1 = __funnelshift_l(x1, x1, (r)); x1 ^= x0; }
    TFR(13) TFR(15) TFR(26) TFR(6)
    x0 += k1;  x1 += ks2 + 1u;
    TFR(17) TFR(29) TFR(16) TFR(24)
    x0 += ks2; x1 += k0 + 2u;
    TFR(13) TFR(15) TFR(26) TFR(6)
    x0 += k0;  x1 += k1 + 3u;
    TFR(17) TFR(29) TFR(16) TFR(24)
    x0 += k1;  x1 += ks2 + 4u;
    TFR(13) TFR(15) TFR(26) TFR(6)
    x0 += ks2; x1 += k0 + 5u;
#undef TFR
    o0 = x0; o1 = x1;
}

__device__ __forceinline__ float draw_uniform(uint2 key, uint32_t j) {
    uint32_t w0, w1;
    tf2x32(key.x, key.y, 0u, j, w0, w1);
    uint32_t bits = w0 ^ w1;
    return __uint_as_float((bits >> 9) | 0x3f800000u) - 1.0f;
}

// ---------------------------------------------------------------------------
// PTRS parameters (exact XLA op ordering, no FMA contraction)
// ---------------------------------------------------------------------------
struct Ptrs { float lam, log_lam, b, a, inv_alpha, v_r, two_a; };

__device__ __forceinline__ Ptrs make_ptrs(float lam) {
    Ptrs p;
    p.lam       = lam;
    p.log_lam   = __nv_logf(lam);
    p.b         = __fadd_rn(0.931f, __fmul_rn(2.53f, __fsqrt_rn(lam)));
    p.a         = __fadd_rn(-0.059f, __fmul_rn(0.02483f, p.b));
    p.inv_alpha = __fadd_rn(1.1239f, __fdiv_rn(1.1328f, __fadd_rn(p.b, -3.4f)));
    p.v_r       = __fadd_rn(0.9277f, -__fdiv_rn(3.6224f, __fadd_rn(p.b, -2.0f)));
    p.two_a     = __fmul_rn(2.0f, p.a);
    return p;
}

// ---------------------------------------------------------------------------
// Init: subkey chains from key(42)=(0,42), foldlike split; reset g_T; effP.
// ---------------------------------------------------------------------------
__global__ void poisson_init_keys() {
    if (threadIdx.x != 0 || blockIdx.x != 0) return;
    g_T = 0;

    uint32_t r0 = 0u, r1 = 42u;                 // knuth: split(rng, 2) chain
    for (int t = 1; t <= TMAX; ++t) {
        uint32_t n0, n1, s0, s1;
        tf2x32(r0, r1, 0u, 0u, n0, n1);
        tf2x32(r0, r1, 0u, 1u, s0, s1);
        g_skK[t] = make_uint2(s0, s1);
        r0 = n0; r1 = n1;
    }
    uint32_t c0 = 0u, c1 = 42u;                 // rejection: split(key, 3) chain
    for (int t = 1; t <= TMAX; ++t) {
        uint32_t n0, n1, a0, a1, b0, b1;
        tf2x32(c0, c1, 0u, 0u, n0, n1);
        tf2x32(c0, c1, 0u, 1u, a0, a1);
        tf2x32(c0, c1, 0u, 2u, b0, b1);
        g_skR0[t] = make_uint2(a0, a1);
        g_skR1[t] = make_uint2(b0, b1);
        c0 = n0; c1 = n1;
    }
    Ptrs e = make_ptrs(1e5f);
    g_effP[0] = e.lam;       g_effP[1] = e.log_lam; g_effP[2] = e.b;
    g_effP[3] = e.a;         g_effP[4] = e.inv_alpha;
    g_effP[5] = e.v_r;       g_effP[6] = e.two_a;
}

// ---------------------------------------------------------------------------
// XLA's Lanczos lgamma (g=7, 8 coeffs), no-reflection path (input >= 1)
// ---------------------------------------------------------------------------
__device__ __forceinline__ float xla_lgamma(float input) {
    float z = __fadd_rn(input, -1.0f);
    float x = 0.99999999999980993f;
    x = __fadd_rn(x, __fdiv_rn( 676.5203681218851f,     __fadd_rn(z, 1.0f)));
    x = __fadd_rn(x, __fdiv_rn(-1259.1392167224028f,    __fadd_rn(z, 2.0f)));
    x = __fadd_rn(x, __fdiv_rn( 771.32342877765313f,    __fadd_rn(z, 3.0f)));
    x = __fadd_rn(x, __fdiv_rn(-176.61502916214059f,    __fadd_rn(z, 4.0f)));
    x = __fadd_rn(x, __fdiv_rn( 12.507343278686905f,    __fadd_rn(z, 5.0f)));
    x = __fadd_rn(x, __fdiv_rn(-0.13857109526572012f,   __fadd_rn(z, 6.0f)));
    x = __fadd_rn(x, __fdiv_rn( 9.9843695780195716e-6f, __fadd_rn(z, 7.0f)));
    x = __fadd_rn(x, __fdiv_rn( 1.5056327351493116e-7f, __fadd_rn(z, 8.0f)));
    float t = __fadd_rn(7.5f, z);
    float log_t = __fadd_rn(2.0149030205422647f, __nv_log1pf(__fdiv_rn(z, 7.5f)));
    float q = __fadd_rn(__fadd_rn(z, 0.5f), -__fdiv_rn(t, log_t));
    return __fadd_rn(__fadd_rn(0.9189385332046727f, __fmul_rn(q, log_t)),
                     __nv_logf(x));
}

__device__ __forceinline__ bool ptrs_try(const Ptrs& p, float u, float v,
                                         float& kf_out) {
    float us = __fadd_rn(0.5f, -fabsf(u));
    float kf = floorf(__fadd_rn(
        __fadd_rn(__fmul_rn(__fadd_rn(__fdiv_rn(p.two_a, us), p.b), u), p.lam),
        0.43f));
    kf_out = kf;
    bool accept1 = (us >= 0.07f) && (v <= p.v_r);
    if (accept1) return true;
    bool reject = (kf < 0.0f) || ((us < 0.013f) && (v > us));
    if (reject) return false;
    float s = __nv_logf(__fdiv_rn(__fmul_rn(v, p.inv_alpha),
                __fadd_rn(__fdiv_rn(p.a, __fmul_rn(us, us)), p.b)));
    float tt = __fadd_rn(__fadd_rn(-p.lam, __fmul_rn(kf, p.log_lam)),
                         -xla_lgamma(__fadd_rn(kf, 1.0f)));
    return (s <= tt);
}

// ---------------------------------------------------------------------------
// Pass 1: T = max over ALL pixels of first-accept iteration (lam_eff = 1e5
// for lam<10). Per-thread task queue: refill on accept -> work ~= mean tries.
// ---------------------------------------------------------------------------
__global__ void __launch_bounds__(BLK)
compute_T_kernel(const float* __restrict__ img, int n) {
    __shared__ uint2 sk0[TMAX + 1], sk1[TMAX + 1];
    __shared__ int warp_max[BLK / 32];
    for (int i = threadIdx.x; i <= TMAX; i += BLK) {
        sk0[i] = g_skR0[i];
        sk1[i] = g_skR1[i];
    }
    __syncthreads();
    Ptrs eff;
    eff.lam = g_effP[0]; eff.log_lam = g_effP[1]; eff.b = g_effP[2];
    eff.a = g_effP[3]; eff.inv_alpha = g_effP[4]; eff.v_r = g_effP[5];
    eff.two_a = g_effP[6];

    int base = blockIdx.x * PPB;
    int tmax_local = 0;
    int round = 0;
    bool active = false;
    Ptrs p; uint32_t ju = 0; int t = 1;

    for (;;) {
        if (!active) {
            bool got = false;
            while (round < CPT) {
                int j = base + round * BLK + (int)threadIdx.x;
                ++round;
                if (j >= n) continue;
                float lam = __fmul_rn(__ldg(img + j), 12.0f);
                p = (lam < 10.0f) ? eff : make_ptrs(lam);
                ju = (uint32_t)j; t = 1; active = true; got = true;
                break;
            }
            if (!got) break;
        }
        float u = __fadd_rn(draw_uniform(sk0[t], ju), -0.5f);
        float v = draw_uniform(sk1[t], ju);
        float kf;
        if (ptrs_try(p, u, v, kf)) {
            tmax_local = max(tmax_local, t);
            active = false;
        } else if (++t > TMAX) {
            active = false;
        }
    }

    __syncwarp();
    int wmax = __reduce_max_sync(0xFFFFFFFFu, tmax_local);
    int wid = threadIdx.x >> 5;
    if ((threadIdx.x & 31) == 0) warp_max[wid] = wmax;
    __syncthreads();
    if (threadIdx.x == 0) {
        int bmax = warp_max[0];
#pragma unroll
        for (int w = 1; w < BLK / 32; ++w) bmax = max(bmax, warp_max[w]);
        atomicMax(&g_T, bmax);
    }
}

// ---------------------------------------------------------------------------
// Pass 2: Knuth via per-thread queue (product form); rejection pixels pushed
// to smem list, processed coherently (down-scan from g_T); outputs staged in
// smem, flushed coalesced.
// ---------------------------------------------------------------------------
__global__ void __launch_bounds__(BLK)
shot_noise_kernel(const float* __restrict__ img, float* __restrict__ out, int n) {
    __shared__ uint2 skK[TMAX + 1], sk0[TMAX + 1], sk1[TMAX + 1];
    __shared__ float obuf[PPB];
    __shared__ int   rejIdx[PPB];
    __shared__ float rejLam[PPB];
    __shared__ int   rejCnt;

    for (int i = threadIdx.x; i <= TMAX; i += BLK) {
        skK[i] = g_skK[i];
        sk0[i] = g_skR0[i];
        sk1[i] = g_skR1[i];
    }
    if (threadIdx.x == 0) rejCnt = 0;
    __syncthreads();

    int base = blockIdx.x * PPB;

    // ---- Phase A: Knuth task queue ----
    bool active = false;
    int round = 0;
    uint32_t ju = 0; int lj = 0, k = 0, t = 1;
    float prod = 1.0f, thresh = 0.0f;

    for (;;) {
        if (!active) {
            bool got = false;
            while (round < CPT) {
                int lidx = round * BLK + (int)threadIdx.x;
                int j = base + lidx;
                ++round;
                if (j >= n) continue;
                float lam = __fmul_rn(__ldg(img + j), 12.0f);
                if (lam >= 10.0f) {
                    int pos = atomicAdd(&rejCnt, 1);
                    rejIdx[pos] = lidx;
                    rejLam[pos] = lam;
                    continue;
                }
                if (lam <= 0.0f) { obuf[lidx] = 0.0f; continue; }
                ju = (uint32_t)j; lj = lidx;
                thresh = __nv_expf(-lam);   // < 1 always (lam >= 1.4e-6)
                prod = 1.0f; k = 0; t = 1;
                active = true; got = true;
                break;
            }
            if (!got) break;
        }
        // One Knuth step: k counts iterations where prod-before > thresh.
        if (prod > thresh && t <= TMAX) {
            ++k;
            prod = __fmul_rn(prod, draw_uniform(skK[t], ju));
            ++t;
        } else {
            obuf[lj] = __fdiv_rn((float)(k - 1), 12.0f);
            active = false;
        }
    }
    __syncthreads();

    // ---- Phase B: rejection pixels (coherent), last accept <= g_T ----
    int cnt = rejCnt;
    int T = g_T;
    for (int i = threadIdx.x; i < cnt; i += BLK) {
        int lidx = rejIdx[i];
        float lam = rejLam[i];
        Ptrs p = make_ptrs(lam);
        uint32_t jr = (uint32_t)(base + lidx);
        float kres = -1.0f;
#pragma unroll 1
        for (int tt = T; tt >= 1; --tt) {
            float u = __fadd_rn(draw_uniform(sk0[tt], jr), -0.5f);
            float v = draw_uniform(sk1[tt], jr);
            float kf;
            if (ptrs_try(p, u, v, kf)) { kres = kf; break; }
        }
        obuf[lidx] = __fdiv_rn(kres, 12.0f);
    }
    __syncthreads();

    // ---- Flush (coalesced) ----
#pragma unroll
    for (int r = 0; r < CPT; ++r) {
        int lidx = r * BLK + (int)threadIdx.x;
        int j = base + lidx;
        if (j < n) out[j] = obuf[lidx];
    }
}

// ---------------------------------------------------------------------------
extern "C" void kernel_launch(void* const* d_in, const int* in_sizes, int n_in,
                              void* d_out, int out_size) {
    const float* img = (const float*)d_in[0];
    float* out = (float*)d_out;
    int n = out_size;
    int blocks = (n + PPB - 1) / PPB;

    poisson_init_keys<<<1, 32>>>();
    compute_T_kernel<<<blocks, BLK>>>(img, n);
    shot_noise_kernel<<<blocks, BLK>>>(img, out, n);
}

// round 4
// speedup vs baseline: 1.3406x; 1.2383x over previous
#include <cuda_runtime.h>
#include <stdint.h>

// ============================================================================
// ShotNoise: out = Poisson(img * 12) / 12, bit-exact vs jax.random.poisson
// (key(42), threefry2x32, partitionable). R4: ILP-4 batched Knuth draws,
// register-capped launch bounds, accept1 fast path without kf divides.
// ============================================================================

extern "C" {
__device__ float __nv_logf(float);
__device__ float __nv_log1pf(float);
__device__ float __nv_expf(float);
}

#define TMAX 64
#define CPT  8
#define BLK  256
#define PPB  (BLK * CPT)

__device__ uint2 g_skK[TMAX + 1];
__device__ uint2 g_skR0[TMAX + 1];
__device__ uint2 g_skR1[TMAX + 1];
__device__ int   g_T;
__device__ float g_effP[7];

// ---------------------------------------------------------------------------
__device__ __forceinline__ void tf2x32(uint32_t k0, uint32_t k1,
                                       uint32_t x0, uint32_t x1,
                                       uint32_t& o0, uint32_t& o1) {
    uint32_t ks2 = k0 ^ k1 ^ 0x1BD11BDAu;
    x0 += k0; x1 += k1;
#define TFR(r) { x0 += x1; x1 = __funnelshift_l(x1, x1, (r)); x1 ^= x0; }
    TFR(13) TFR(15) TFR(26) TFR(6)
    x0 += k1;  x1 += ks2 + 1u;
    TFR(17) TFR(29) TFR(16) TFR(24)
    x0 += ks2; x1 += k0 + 2u;
    TFR(13) TFR(15) TFR(26) TFR(6)
    x0 += k0;  x1 += k1 + 3u;
    TFR(17) TFR(29) TFR(16) TFR(24)
    x0 += k1;  x1 += ks2 + 4u;
    TFR(13) TFR(15) TFR(26) TFR(6)
    x0 += ks2; x1 += k0 + 5u;
#undef TFR
    o0 = x0; o1 = x1;
}

__device__ __forceinline__ float bits_to_u01(uint32_t bits) {
    return __uint_as_float((bits >> 9) | 0x3f800000u) - 1.0f;
}

__device__ __forceinline__ float draw_uniform(uint2 key, uint32_t j) {
    uint32_t w0, w1;
    tf2x32(key.x, key.y, 0u, j, w0, w1);
    return bits_to_u01(w0 ^ w1);
}

// ---------------------------------------------------------------------------
struct Ptrs { float lam, log_lam, b, a, inv_alpha, v_r, two_a; };

__device__ __forceinline__ Ptrs make_ptrs(float lam) {
    Ptrs p;
    p.lam       = lam;
    p.log_lam   = __nv_logf(lam);
    p.b         = __fadd_rn(0.931f, __fmul_rn(2.53f, __fsqrt_rn(lam)));
    p.a         = __fadd_rn(-0.059f, __fmul_rn(0.02483f, p.b));
    p.inv_alpha = __fadd_rn(1.1239f, __fdiv_rn(1.1328f, __fadd_rn(p.b, -3.4f)));
    p.v_r       = __fadd_rn(0.9277f, -__fdiv_rn(3.6224f, __fadd_rn(p.b, -2.0f)));
    p.two_a     = __fmul_rn(2.0f, p.a);
    return p;
}

// ---------------------------------------------------------------------------
__global__ void poisson_init_keys() {
    if (threadIdx.x != 0 || blockIdx.x != 0) return;
    g_T = 0;

    uint32_t r0 = 0u, r1 = 42u;
    for (int t = 1; t <= TMAX; ++t) {
        uint32_t n0, n1, s0, s1;
        tf2x32(r0, r1, 0u, 0u, n0, n1);
        tf2x32(r0, r1, 0u, 1u, s0, s1);
        g_skK[t] = make_uint2(s0, s1);
        r0 = n0; r1 = n1;
    }
    uint32_t c0 = 0u, c1 = 42u;
    for (int t = 1; t <= TMAX; ++t) {
        uint32_t n0, n1, a0, a1, b0, b1;
        tf2x32(c0, c1, 0u, 0u, n0, n1);
        tf2x32(c0, c1, 0u, 1u, a0, a1);
        tf2x32(c0, c1, 0u, 2u, b0, b1);
        g_skR0[t] = make_uint2(a0, a1);
        g_skR1[t] = make_uint2(b0, b1);
        c0 = n0; c1 = n1;
    }
    Ptrs e = make_ptrs(1e5f);
    g_effP[0] = e.lam; g_effP[1] = e.log_lam; g_effP[2] = e.b;
    g_effP[3] = e.a;   g_effP[4] = e.inv_alpha;
    g_effP[5] = e.v_r; g_effP[6] = e.two_a;
}

// ---------------------------------------------------------------------------
__device__ __forceinline__ float xla_lgamma(float input) {
    float z = __fadd_rn(input, -1.0f);
    float x = 0.99999999999980993f;
    x = __fadd_rn(x, __fdiv_rn( 676.5203681218851f,     __fadd_rn(z, 1.0f)));
    x = __fadd_rn(x, __fdiv_rn(-1259.1392167224028f,    __fadd_rn(z, 2.0f)));
    x = __fadd_rn(x, __fdiv_rn( 771.32342877765313f,    __fadd_rn(z, 3.0f)));
    x = __fadd_rn(x, __fdiv_rn(-176.61502916214059f,    __fadd_rn(z, 4.0f)));
    x = __fadd_rn(x, __fdiv_rn( 12.507343278686905f,    __fadd_rn(z, 5.0f)));
    x = __fadd_rn(x, __fdiv_rn(-0.13857109526572012f,   __fadd_rn(z, 6.0f)));
    x = __fadd_rn(x, __fdiv_rn( 9.9843695780195716e-6f, __fadd_rn(z, 7.0f)));
    x = __fadd_rn(x, __fdiv_rn( 1.5056327351493116e-7f, __fadd_rn(z, 8.0f)));
    float t = __fadd_rn(7.5f, z);
    float log_t = __fadd_rn(2.0149030205422647f, __nv_log1pf(__fdiv_rn(z, 7.5f)));
    float q = __fadd_rn(__fadd_rn(z, 0.5f), -__fdiv_rn(t, log_t));
    return __fadd_rn(__fadd_rn(0.9189385332046727f, __fmul_rn(q, log_t)),
                     __nv_logf(x));
}

// Full try (returns accept + kf) — used where kf is needed (phase B).
__device__ __forceinline__ bool ptrs_try(const Ptrs& p, float u, float v,
                                         float& kf_out) {
    float us = __fadd_rn(0.5f, -fabsf(u));
    float kf = floorf(__fadd_rn(
        __fadd_rn(__fmul_rn(__fadd_rn(__fdiv_rn(p.two_a, us), p.b), u), p.lam),
        0.43f));
    kf_out = kf;
    bool accept1 = (us >= 0.07f) && (v <= p.v_r);
    if (accept1) return true;
    bool reject = (kf < 0.0f) || ((us < 0.013f) && (v > us));
    if (reject) return false;
    float s = __nv_logf(__fdiv_rn(__fmul_rn(v, p.inv_alpha),
                __fadd_rn(__fdiv_rn(p.a, __fmul_rn(us, us)), p.b)));
    float tt = __fadd_rn(__fadd_rn(-p.lam, __fmul_rn(kf, p.log_lam)),
                         -xla_lgamma(__fadd_rn(kf, 1.0f)));
    return (s <= tt);
}

// Accept-only try (no kf on the 79% accept1 fast path) — pass 1.
__device__ __forceinline__ bool ptrs_accept(const Ptrs& p, float u, float v) {
    float us = __fadd_rn(0.5f, -fabsf(u));
    bool accept1 = (us >= 0.07f) && (v <= p.v_r);
    if (accept1) return true;
    float kf = floorf(__fadd_rn(
        __fadd_rn(__fmul_rn(__fadd_rn(__fdiv_rn(p.two_a, us), p.b), u), p.lam),
        0.43f));
    bool reject = (kf < 0.0f) || ((us < 0.013f) && (v > us));
    if (reject) return false;
    float s = __nv_logf(__fdiv_rn(__fmul_rn(v, p.inv_alpha),
                __fadd_rn(__fdiv_rn(p.a, __fmul_rn(us, us)), p.b)));
    float tt = __fadd_rn(__fadd_rn(-p.lam, __fmul_rn(kf, p.log_lam)),
                         -xla_lgamma(__fadd_rn(kf, 1.0f)));
    return (s <= tt);
}

// ---------------------------------------------------------------------------
// Pass 1: T = max first-accept iteration over all pixels (lam_eff=1e5 mask).
// ---------------------------------------------------------------------------
__global__ void __launch_bounds__(BLK, 4)
compute_T_kernel(const float* __restrict__ img, int n) {
    __shared__ uint2 sk0[TMAX + 1], sk1[TMAX + 1];
    __shared__ int warp_max[BLK / 32];
    for (int i = threadIdx.x; i <= TMAX; i += BLK) {
        sk0[i] = g_skR0[i];
        sk1[i] = g_skR1[i];
    }
    __syncthreads();
    Ptrs eff;
    eff.lam = g_effP[0]; eff.log_lam = g_effP[1]; eff.b = g_effP[2];
    eff.a = g_effP[3]; eff.inv_alpha = g_effP[4]; eff.v_r = g_effP[5];
    eff.two_a = g_effP[6];

    int base = blockIdx.x * PPB;
    int tmax_local = 0;
    int round = 0;
    bool active = false;
    Ptrs p; uint32_t ju = 0; int t = 1;

    for (;;) {
        if (!active) {
            bool got = false;
            while (round < CPT) {
                int j = base + round * BLK + (int)threadIdx.x;
                ++round;
                if (j >= n) continue;
                float lam = __fmul_rn(__ldg(img + j), 12.0f);
                p = (lam < 10.0f) ? eff : make_ptrs(lam);
                ju = (uint32_t)j; t = 1; active = true; got = true;
                break;
            }
            if (!got) break;
        }
        float u = __fadd_rn(draw_uniform(sk0[t], ju), -0.5f);
        float v = draw_uniform(sk1[t], ju);
        if (ptrs_accept(p, u, v)) {
            tmax_local = max(tmax_local, t);
            active = false;
        } else if (++t > TMAX) {
            active = false;
        }
    }

    __syncwarp();
    int wmax = __reduce_max_sync(0xFFFFFFFFu, tmax_local);
    int wid = threadIdx.x >> 5;
    if ((threadIdx.x & 31) == 0) warp_max[wid] = wmax;
    __syncthreads();
    if (threadIdx.x == 0) {
        int bmax = warp_max[0];
#pragma unroll
        for (int w = 1; w < BLK / 32; ++w) bmax = max(bmax, warp_max[w]);
        atomicMax(&g_T, bmax);
    }
}

// ---------------------------------------------------------------------------
// Pass 2: Knuth with ILP-4 batched draws via task queue; rejection pixels
// compacted to smem and processed coherently; coalesced output flush.
// ---------------------------------------------------------------------------
__global__ void __launch_bounds__(BLK, 4)
shot_noise_kernel(const float* __restrict__ img, float* __restrict__ out, int n) {
    __shared__ uint2 skK[TMAX + 1], sk0[TMAX + 1], sk1[TMAX + 1];
    __shared__ float obuf[PPB];
    __shared__ int   rejIdx[PPB];
    __shared__ float rejLam[PPB];
    __shared__ int   rejCnt;

    for (int i = threadIdx.x; i <= TMAX; i += BLK) {
        skK[i] = g_skK[i];
        sk0[i] = g_skR0[i];
        sk1[i] = g_skR1[i];
    }
    if (threadIdx.x == 0) rejCnt = 0;
    __syncthreads();

    int base = blockIdx.x * PPB;

    // ---- Phase A: Knuth, 4 draws per trip (independent threefry => ILP 4) ----
    bool active = false;
    int round = 0;
    uint32_t ju = 0; int lj = 0, k = 0, t = 1;
    float prod = 1.0f, thresh = 0.0f;

    for (;;) {
        if (!active) {
            bool got = false;
            while (round < CPT) {
                int lidx = round * BLK + (int)threadIdx.x;
                int j = base + lidx;
                ++round;
                if (j >= n) continue;
                float lam = __fmul_rn(__ldg(img + j), 12.0f);
                if (lam >= 10.0f) {
                    int pos = atomicAdd(&rejCnt, 1);
                    rejIdx[pos] = lidx;
                    rejLam[pos] = lam;
                    continue;
                }
                if (lam <= 0.0f) { obuf[lidx] = 0.0f; continue; }
                ju = (uint32_t)j; lj = lidx;
                thresh = __nv_expf(-lam);
                prod = 1.0f; k = 0; t = 1;
                active = true; got = true;
                break;
            }
            if (!got) break;
        }
        // 4 independent draws at t..t+3 (clamped; P(need>64) ~ 0).
        int t0 = min(t, TMAX), t1 = min(t + 1, TMAX);
        int t2 = min(t + 2, TMAX), t3 = min(t + 3, TMAX);
        uint2 k0 = skK[t0], k1 = skK[t1], k2 = skK[t2], k3 = skK[t3];
        uint32_t a0, b0, a1, b1, a2, b2, a3, b3;
        tf2x32(k0.x, k0.y, 0u, ju, a0, b0);
        tf2x32(k1.x, k1.y, 0u, ju, a1, b1);
        tf2x32(k2.x, k2.y, 0u, ju, a2, b2);
        tf2x32(k3.x, k3.y, 0u, ju, a3, b3);
        float u0 = bits_to_u01(a0 ^ b0), u1 = bits_to_u01(a1 ^ b1);
        float u2 = bits_to_u01(a2 ^ b2), u3 = bits_to_u01(a3 ^ b3);
        // Gated accumulate: monotone prod => gate self-masks (matches JAX).
        bool c;
        c = prod > thresh; k += c; prod = c ? __fmul_rn(prod, u0) : prod;
        c = prod > thresh; k += c; prod = c ? __fmul_rn(prod, u1) : prod;
        c = prod > thresh; k += c; prod = c ? __fmul_rn(prod, u2) : prod;
        c = prod > thresh; k += c; prod = c ? __fmul_rn(prod, u3) : prod;
        t += 4;
        if (prod <= thresh || t > TMAX) {
            obuf[lj] = __fdiv_rn((float)(k - 1), 12.0f);
            active = false;
        }
    }
    __syncthreads();

    // ---- Phase B: rejection pixels, last accept <= g_T (down-scan) ----
    int cnt = rejCnt;
    int T = g_T;
    for (int i = threadIdx.x; i < cnt; i += BLK) {
        int lidx = rejIdx[i];
        float lam = rejLam[i];
        Ptrs p = make_ptrs(lam);
        uint32_t jr = (uint32_t)(base + lidx);
        float kres = -1.0f;
#pragma unroll 1
        for (int tt = T; tt >= 1; --tt) {
            float u = __fadd_rn(draw_uniform(sk0[tt], jr), -0.5f);
            float v = draw_uniform(sk1[tt], jr);
            float kf;
            if (ptrs_try(p, u, v, kf)) { kres = kf; break; }
        }
        obuf[lidx] = __fdiv_rn(kres, 12.0f);
    }
    __syncthreads();

    // ---- Flush (coalesced) ----
#pragma unroll
    for (int r = 0; r < CPT; ++r) {
        int lidx = r * BLK + (int)threadIdx.x;
        int j = base + lidx;
        if (j < n) out[j] = obuf[lidx];
    }
}

// ---------------------------------------------------------------------------
extern "C" void kernel_launch(void* const* d_in, const int* in_sizes, int n_in,
                              void* d_out, int out_size) {
    const float* img = (const float*)d_in[0];
    float* out = (float*)d_out;
    int n = out_size;
    int blocks = (n + PPB - 1) / PPB;

    poisson_init_keys<<<1, 32>>>();
    compute_T_kernel<<<blocks, BLK>>>(img, n);
    shot_noise_kernel<<<blocks, BLK>>>(img, out, n);
}

// round 5
// speedup vs baseline: 1.3489x; 1.0061x over previous
#include <cuda_runtime.h>
#include <stdint.h>

// ============================================================================
// ShotNoise: out = Poisson(img * 12) / 12, bit-exact vs jax.random.poisson
// (key(42), threefry2x32, partitionable). R5: pipe-rebalanced threefry
// (chain adds forced onto FMA pipe via IMAD), precomputed ks2 in key tables,
// nop kernel prepended to land ncu sampling on a hot kernel.
// ============================================================================

extern "C" {
__device__ float __nv_logf(float);
__device__ float __nv_log1pf(float);
__device__ float __nv_expf(float);
}

#define TMAX 64
#define CPT  8
#define BLK  256
#define PPB  (BLK * CPT)

__device__ uint4 g_kK[TMAX + 1];    // (k0, k1, ks2, 0) knuth subkeys
__device__ uint4 g_kR0[TMAX + 1];   // rejection subkey_0
__device__ uint4 g_kR1[TMAX + 1];   // rejection subkey_1
__device__ int   g_T;
__device__ float g_effP[7];

// force an integer add onto the FMA pipe (IMAD): r = a*one + b, one==1 opaque
__device__ __forceinline__ uint32_t imadd(uint32_t a, uint32_t one, uint32_t b) {
    uint32_t r;
    asm("mad.lo.u32 %0, %1, %2, %3;" : "=r"(r) : "r"(a), "r"(one), "r"(b));
    return r;
}

// ---------------------------------------------------------------------------
// plain threefry2x32 (init kernel only)
// ---------------------------------------------------------------------------
__device__ __forceinline__ void tf2x32(uint32_t k0, uint32_t k1,
                                       uint32_t x0, uint32_t x1,
                                       uint32_t& o0, uint32_t& o1) {
    uint32_t ks2 = k0 ^ k1 ^ 0x1BD11BDAu;
    x0 += k0; x1 += k1;
#define TFR(r) { x0 += x1; x1 = __funnelshift_l(x1, x1, (r)); x1 ^= x0; }
    TFR(13) TFR(15) TFR(26) TFR(6)
    x0 += k1;  x1 += ks2 + 1u;
    TFR(17) TFR(29) TFR(16) TFR(24)
    x0 += ks2; x1 += k0 + 2u;
    TFR(13) TFR(15) TFR(26) TFR(6)
    x0 += k0;  x1 += k1 + 3u;
    TFR(17) TFR(29) TFR(16) TFR(24)
    x0 += k1;  x1 += ks2 + 4u;
    TFR(13) TFR(15) TFR(26) TFR(6)
    x0 += ks2; x1 += k0 + 5u;
#undef TFR
    o0 = x0; o1 = x1;
}

// ---------------------------------------------------------------------------
// hot-path threefry: counter (0, j), key from uint4 (k0,k1,ks2), chain adds
// on FMA pipe via imadd. Returns folded bits w0^w1.
// ---------------------------------------------------------------------------
__device__ __forceinline__ uint32_t tf_fold(uint4 K, uint32_t j, uint32_t one) {
    uint32_t k0 = K.x, k1 = K.y, ks2 = K.z;
    uint32_t x0 = k0;              // 0 + k0
    uint32_t x1 = j + k1;
#define TFR(r) { x0 = imadd(x0, one, x1); \
                 x1 = __funnelshift_l(x1, x1, (r)); x1 ^= x0; }
    TFR(13) TFR(15) TFR(26) TFR(6)
    x0 += k1;  x1 = x1 + ks2 + 1u;
    TFR(17) TFR(29) TFR(16) TFR(24)
    x0 += ks2; x1 = x1 + k0 + 2u;
    TFR(13) TFR(15) TFR(26) TFR(6)
    x0 += k0;  x1 = x1 + k1 + 3u;
    TFR(17) TFR(29) TFR(16) TFR(24)
    x0 += k1;  x1 = x1 + ks2 + 4u;
    TFR(13) TFR(15) TFR(26) TFR(6)
    x0 += ks2; x1 = x1 + k0 + 5u;
#undef TFR
    return x0 ^ x1;
}

__device__ __forceinline__ float bits_to_u01(uint32_t bits) {
    return __uint_as_float((bits >> 9) | 0x3f800000u) - 1.0f;
}

__device__ __forceinline__ float draw_u(uint4 K, uint32_t j, uint32_t one) {
    return bits_to_u01(tf_fold(K, j, one));
}

// ---------------------------------------------------------------------------
struct Ptrs { float lam, log_lam, b, a, inv_alpha, v_r, two_a; };

__device__ __forceinline__ Ptrs make_ptrs(float lam) {
    Ptrs p;
    p.lam       = lam;
    p.log_lam   = __nv_logf(lam);
    p.b         = __fadd_rn(0.931f, __fmul_rn(2.53f, __fsqrt_rn(lam)));
    p.a         = __fadd_rn(-0.059f, __fmul_rn(0.02483f, p.b));
    p.inv_alpha = __fadd_rn(1.1239f, __fdiv_rn(1.1328f, __fadd_rn(p.b, -3.4f)));
    p.v_r       = __fadd_rn(0.9277f, -__fdiv_rn(3.6224f, __fadd_rn(p.b, -2.0f)));
    p.two_a     = __fmul_rn(2.0f, p.a);
    return p;
}

// ---------------------------------------------------------------------------
__global__ void nop_kernel() {}

__global__ void poisson_init_keys() {
    if (threadIdx.x != 0 || blockIdx.x != 0) return;
    g_T = 0;

    uint32_t r0 = 0u, r1 = 42u;
    for (int t = 1; t <= TMAX; ++t) {
        uint32_t n0, n1, s0, s1;
        tf2x32(r0, r1, 0u, 0u, n0, n1);
        tf2x32(r0, r1, 0u, 1u, s0, s1);
        g_kK[t] = make_uint4(s0, s1, s0 ^ s1 ^ 0x1BD11BDAu, 0u);
        r0 = n0; r1 = n1;
    }
    uint32_t c0 = 0u, c1 = 42u;
    for (int t = 1; t <= TMAX; ++t) {
        uint32_t n0, n1, a0, a1, b0, b1;
        tf2x32(c0, c1, 0u, 0u, n0, n1);
        tf2x32(c0, c1, 0u, 1u, a0, a1);
        tf2x32(c0, c1, 0u, 2u, b0, b1);
        g_kR0[t] = make_uint4(a0, a1, a0 ^ a1 ^ 0x1BD11BDAu, 0u);
        g_kR1[t] = make_uint4(b0, b1, b0 ^ b1 ^ 0x1BD11BDAu, 0u);
        c0 = n0; c1 = n1;
    }
    Ptrs e = make_ptrs(1e5f);
    g_effP[0] = e.lam; g_effP[1] = e.log_lam; g_effP[2] = e.b;
    g_effP[3] = e.a;   g_effP[4] = e.inv_alpha;
    g_effP[5] = e.v_r; g_effP[6] = e.two_a;
}

// ---------------------------------------------------------------------------
__device__ __forceinline__ float xla_lgamma(float input) {
    float z = __fadd_rn(input, -1.0f);
    float x = 0.99999999999980993f;
    x = __fadd_rn(x, __fdiv_rn( 676.5203681218851f,     __fadd_rn(z, 1.0f)));
    x = __fadd_rn(x, __fdiv_rn(-1259.1392167224028f,    __fadd_rn(z, 2.0f)));
    x = __fadd_rn(x, __fdiv_rn( 771.32342877765313f,    __fadd_rn(z, 3.0f)));
    x = __fadd_rn(x, __fdiv_rn(-176.61502916214059f,    __fadd_rn(z, 4.0f)));
    x = __fadd_rn(x, __fdiv_rn( 12.507343278686905f,    __fadd_rn(z, 5.0f)));
    x = __fadd_rn(x, __fdiv_rn(-0.13857109526572012f,   __fadd_rn(z, 6.0f)));
    x = __fadd_rn(x, __fdiv_rn( 9.9843695780195716e-6f, __fadd_rn(z, 7.0f)));
    x = __fadd_rn(x, __fdiv_rn( 1.5056327351493116e-7f, __fadd_rn(z, 8.0f)));
    float t = __fadd_rn(7.5f, z);
    float log_t = __fadd_rn(2.0149030205422647f, __nv_log1pf(__fdiv_rn(z, 7.5f)));
    float q = __fadd_rn(__fadd_rn(z, 0.5f), -__fdiv_rn(t, log_t));
    return __fadd_rn(__fadd_rn(0.9189385332046727f, __fmul_rn(q, log_t)),
                     __nv_logf(x));
}

__device__ __forceinline__ bool ptrs_try(const Ptrs& p, float u, float v,
                                         float& kf_out) {
    float us = __fadd_rn(0.5f, -fabsf(u));
    float kf = floorf(__fadd_rn(
        __fadd_rn(__fmul_rn(__fadd_rn(__fdiv_rn(p.two_a, us), p.b), u), p.lam),
        0.43f));
    kf_out = kf;
    bool accept1 = (us >= 0.07f) && (v <= p.v_r);
    if (accept1) return true;
    bool reject = (kf < 0.0f) || ((us < 0.013f) && (v > us));
    if (reject) return false;
    float s = __nv_logf(__fdiv_rn(__fmul_rn(v, p.inv_alpha),
                __fadd_rn(__fdiv_rn(p.a, __fmul_rn(us, us)), p.b)));
    float tt = __fadd_rn(__fadd_rn(-p.lam, __fmul_rn(kf, p.log_lam)),
                         -xla_lgamma(__fadd_rn(kf, 1.0f)));
    return (s <= tt);
}

__device__ __forceinline__ bool ptrs_accept(const Ptrs& p, float u, float v) {
    float us = __fadd_rn(0.5f, -fabsf(u));
    bool accept1 = (us >= 0.07f) && (v <= p.v_r);
    if (accept1) return true;
    float kf = floorf(__fadd_rn(
        __fadd_rn(__fmul_rn(__fadd_rn(__fdiv_rn(p.two_a, us), p.b), u), p.lam),
        0.43f));
    bool reject = (kf < 0.0f) || ((us < 0.013f) && (v > us));
    if (reject) return false;
    float s = __nv_logf(__fdiv_rn(__fmul_rn(v, p.inv_alpha),
                __fadd_rn(__fdiv_rn(p.a, __fmul_rn(us, us)), p.b)));
    float tt = __fadd_rn(__fadd_rn(-p.lam, __fmul_rn(kf, p.log_lam)),
                         -xla_lgamma(__fadd_rn(kf, 1.0f)));
    return (s <= tt);
}

// ---------------------------------------------------------------------------
// Pass 1: T = max first-accept iteration over all pixels (lam_eff=1e5 mask).
// ---------------------------------------------------------------------------
__global__ void __launch_bounds__(BLK, 4)
compute_T_kernel(const float* __restrict__ img, int n) {
    __shared__ uint4 sk0[TMAX + 1], sk1[TMAX + 1];
    __shared__ int warp_max[BLK / 32];
    for (int i = threadIdx.x; i <= TMAX; i += BLK) {
        sk0[i] = g_kR0[i];
        sk1[i] = g_kR1[i];
    }
    __syncthreads();
    uint32_t one = min(blockDim.x, 1u);   // ==1, opaque to compiler
    Ptrs eff;
    eff.lam = g_effP[0]; eff.log_lam = g_effP[1]; eff.b = g_effP[2];
    eff.a = g_effP[3]; eff.inv_alpha = g_effP[4]; eff.v_r = g_effP[5];
    eff.two_a = g_effP[6];

    int base = blockIdx.x * PPB;
    int tmax_local = 0;
    int round = 0;
    bool active = false;
    Ptrs p; uint32_t ju = 0; int t = 1;

    for (;;) {
        if (!active) {
            bool got = false;
            while (round < CPT) {
                int j = base + round * BLK + (int)threadIdx.x;
                ++round;
                if (j >= n) continue;
                float lam = __fmul_rn(__ldg(img + j), 12.0f);
                p = (lam < 10.0f) ? eff : make_ptrs(lam);
                ju = (uint32_t)j; t = 1; active = true; got = true;
                break;
            }
            if (!got) break;
        }
        float u = __fadd_rn(draw_u(sk0[t], ju, one), -0.5f);
        float v = draw_u(sk1[t], ju, one);
        if (ptrs_accept(p, u, v)) {
            tmax_local = max(tmax_local, t);
            active = false;
        } else if (++t > TMAX) {
            active = false;
        }
    }

    __syncwarp();
    int wmax = __reduce_max_sync(0xFFFFFFFFu, tmax_local);
    int wid = threadIdx.x >> 5;
    if ((threadIdx.x & 31) == 0) warp_max[wid] = wmax;
    __syncthreads();
    if (threadIdx.x == 0) {
        int bmax = warp_max[0];
#pragma unroll
        for (int w = 1; w < BLK / 32; ++w) bmax = max(bmax, warp_max[w]);
        atomicMax(&g_T, bmax);
    }
}

// ---------------------------------------------------------------------------
// Pass 2: Knuth ILP-4 batched draws via task queue; rejection pixels
// compacted to smem and processed coherently; coalesced output flush.
// ---------------------------------------------------------------------------
__global__ void __launch_bounds__(BLK, 4)
shot_noise_kernel(const float* __restrict__ img, float* __restrict__ out, int n) {
    __shared__ uint4 skK[TMAX + 1], sk0[TMAX + 1], sk1[TMAX + 1];
    __shared__ float obuf[PPB];
    __shared__ int   rejIdx[PPB];
    __shared__ float rejLam[PPB];
    __shared__ int   rejCnt;

    for (int i = threadIdx.x; i <= TMAX; i += BLK) {
        skK[i] = g_kK[i];
        sk0[i] = g_kR0[i];
        sk1[i] = g_kR1[i];
    }
    if (threadIdx.x == 0) rejCnt = 0;
    __syncthreads();
    uint32_t one = min(blockDim.x, 1u);

    int base = blockIdx.x * PPB;

    // ---- Phase A: Knuth, 4 draws per trip ----
    bool active = false;
    int round = 0;
    uint32_t ju = 0; int lj = 0, k = 0, t = 1;
    float prod = 1.0f, thresh = 0.0f;

    for (;;) {
        if (!active) {
            bool got = false;
            while (round < CPT) {
                int lidx = round * BLK + (int)threadIdx.x;
                int j = base + lidx;
                ++round;
                if (j >= n) continue;
                float lam = __fmul_rn(__ldg(img + j), 12.0f);
                if (lam >= 10.0f) {
                    int pos = atomicAdd(&rejCnt, 1);
                    rejIdx[pos] = lidx;
                    rejLam[pos] = lam;
                    continue;
                }
                if (lam <= 0.0f) { obuf[lidx] = 0.0f; continue; }
                ju = (uint32_t)j; lj = lidx;
                thresh = __nv_expf(-lam);
                prod = 1.0f; k = 0; t = 1;
                active = true; got = true;
                break;
            }
            if (!got) break;
        }
        int t0 = min(t, TMAX), t1 = min(t + 1, TMAX);
        int t2 = min(t + 2, TMAX), t3 = min(t + 3, TMAX);
        float u0 = bits_to_u01(tf_fold(skK[t0], ju, one));
        float u1 = bits_to_u01(tf_fold(skK[t1], ju, one));
        float u2 = bits_to_u01(tf_fold(skK[t2], ju, one));
        float u3 = bits_to_u01(tf_fold(skK[t3], ju, one));
        bool c;
        c = prod > thresh; k += c; prod = c ? __fmul_rn(prod, u0) : prod;
        c = prod > thresh; k += c; prod = c ? __fmul_rn(prod, u1) : prod;
        c = prod > thresh; k += c; prod = c ? __fmul_rn(prod, u2) : prod;
        c = prod > thresh; k += c; prod = c ? __fmul_rn(prod, u3) : prod;
        t += 4;
        if (prod <= thresh || t > TMAX) {
            obuf[lj] = __fdiv_rn((float)(k - 1), 12.0f);
            active = false;
        }
    }
    __syncthreads();

    // ---- Phase B: rejection pixels, last accept <= g_T (down-scan) ----
    int cnt = rejCnt;
    int T = g_T;
    for (int i = threadIdx.x; i < cnt; i += BLK) {
        int lidx = rejIdx[i];
        float lam = rejLam[i];
        Ptrs p = make_ptrs(lam);
        uint32_t jr = (uint32_t)(base + lidx);
        float kres = -1.0f;
#pragma unroll 1
        for (int tt = T; tt >= 1; --tt) {
            float u = __fadd_rn(draw_u(sk0[tt], jr, one), -0.5f);
            float v = draw_u(sk1[tt], jr, one);
            float kf;
            if (ptrs_try(p, u, v, kf)) { kres = kf; break; }
        }
        obuf[lidx] = __fdiv_rn(kres, 12.0f);
    }
    __syncthreads();

    // ---- Flush (coalesced) ----
#pragma unroll
    for (int r = 0; r < CPT; ++r) {
        int lidx = r * BLK + (int)threadIdx.x;
        int j = base + lidx;
        if (j < n) out[j] = obuf[lidx];
    }
}

// ---------------------------------------------------------------------------
extern "C" void kernel_launch(void* const* d_in, const int* in_sizes, int n_in,
                              void* d_out, int out_size) {
    const float* img = (const float*)d_in[0];
    float* out = (float*)d_out;
    int n = out_size;
    int blocks = (n + PPB - 1) / PPB;

    nop_kernel<<<1, 32>>>();           // shifts ncu -s window onto a hot kernel
    poisson_init_keys<<<1, 32>>>();
    compute_T_kernel<<<blocks, BLK>>>(img, n);
    shot_noise_kernel<<<blocks, BLK>>>(img, out, n);
}